// round 1
// baseline (speedup 1.0000x reference)
#include <cuda_runtime.h>

// InverseHaarTransform: out[b,c] = sum over 4 bands of
// conv2x2(zeropad_topleft(bilinear2x(x[b, band*3+c])), f_band)
// Collapsed analytically to a separable 3x3 stencil on the 512-res input.
//
// 1D primitives (unscaled; all scale factors folded into final weights):
//   L-horizontal: he = a+b            ho = a + 6b + c     (deferred 1, 0.25)
//   G-horizontal: ge = a-b            go = a - c          (deferred 0.5, 0.25)
//   same forms vertically.
// Band types: 0=ll (Lv,Lh)  1=-lh (Gv,Lh)  2=-hl (Lv,Gh)  3=hh (Gv,Gh)
// Zero-pad boundary (up[-1]=0): at y==0 / x==0 the EVEN primitive becomes
//   s1 (L-type) or -2*s1 (G-type). Clamped loads handle all other edges.

#define YS 32          // rows of input processed per thread (strip length)
#define H_IN 512
#define W_IN 512

__global__ __launch_bounds__(256, 2)
void ihaar_kernel(const float* __restrict__ x,
                  const float* __restrict__ f0,
                  const float* __restrict__ f1,
                  const float* __restrict__ f2,
                  const float* __restrict__ f3,
                  float* __restrict__ out)
{
    const int gx  = threadIdx.x;         // 0..255 : column pair index
    const int z   = blockIdx.z;          // 0..47  : b*3 + c
    const int b   = z / 3;
    const int cch = z - 3 * b;
    const int y0  = blockIdx.y * YS;

    const int  x2 = gx * 2;              // first input column owned
    const int  xm = (x2 == 0) ? 0 : (x2 - 1);
    const int  xp = (x2 + 2 > W_IN - 1) ? (W_IN - 1) : (x2 + 2);
    const bool xe = (x2 == 0);

    const float* pl[4];
#pragma unroll
    for (int k = 0; k < 4; ++k)
        pl[k] = x + ((size_t)(b * 12 + k * 3 + cch) << 18);   // * 512*512

    float* op = out + ((size_t)z << 20);                       // * 1024*1024

    // Band scale = f[0][0] of each registered filter (s^2 = 0.5 for Haar).
    const float sA = __ldg(f0), sB = __ldg(f1), sC = __ldg(f2), sD = __ldg(f3);

    // Quadrant weights: W[band] = scale * defV(type_v, pi) * defH(type_h, pj)
    // defL: even 1, odd 0.25 ; defG: even 0.5, odd 0.25
    const float W00[4] = {        sA, 0.5f   * sB, 0.5f   * sC, 0.25f  * sD };
    const float W01[4] = { 0.25f* sA, 0.125f * sB, 0.25f  * sC, 0.125f * sD };
    const float W10[4] = { 0.25f* sA, 0.25f  * sB, 0.125f * sC, 0.125f * sD };
    const float W11[4] = { 0.0625f*sA, 0.0625f*sB, 0.0625f*sC, 0.0625f*sD };

    // Rolling 3-row window of horizontal combos, per band, per owned column.
    float he[4][3][2];   // even-parity horizontal primitive
    float ho[4][3][2];   // odd-parity horizontal primitive

    auto loadrow = [&](int ry, int s) {
#pragma unroll
        for (int k = 0; k < 4; ++k) {
            const float* row = pl[k] + ry * W_IN;
            float  m0 = __ldg(row + xm);
            float2 mm = __ldg((const float2*)(row + x2));
            float  m1 = mm.x, m2 = mm.y;
            float  m3 = __ldg(row + xp);
            if (k < 2) {          // L horizontal (ll, -lh)
                he[k][s][0] = xe ? m1 : (m0 + m1);
                he[k][s][1] = m1 + m2;
                ho[k][s][0] = fmaf(6.f, m1, m0 + m2);
                ho[k][s][1] = fmaf(6.f, m2, m1 + m3);
            } else {              // G horizontal (-hl, hh)
                he[k][s][0] = xe ? (-2.f * m1) : (m0 - m1);
                he[k][s][1] = m1 - m2;
                ho[k][s][0] = m0 - m2;
                ho[k][s][1] = m1 - m3;
            }
        }
    };

    loadrow((y0 == 0) ? 0 : (y0 - 1), 0);
    loadrow(y0, 1);

    for (int yy = 0; yy < YS; ++yy) {
        const int  y   = y0 + yy;
        const int  yn  = (y + 1 > H_IN - 1) ? (H_IN - 1) : (y + 1);
        const bool top = (y == 0);
        loadrow(yn, 2);

        float a00[2], a01[2], a10[2], a11[2];
#pragma unroll
        for (int c = 0; c < 2; ++c) {
            float acc00 = 0.f, acc01 = 0.f, acc10 = 0.f, acc11 = 0.f;
#pragma unroll
            for (int k = 0; k < 4; ++k) {
                const float se0 = he[k][0][c], se1 = he[k][1][c], se2 = he[k][2][c];
                const float so0 = ho[k][0][c], so1 = ho[k][1][c], so2 = ho[k][2][c];
                float qee, qeo, qoe, qoo;
                if (k & 1) {      // G vertical (-lh, hh)
                    qee = top ? (-2.f * se1) : (se0 - se1);
                    qeo = top ? (-2.f * so1) : (so0 - so1);
                    qoe = se0 - se2;
                    qoo = so0 - so2;
                } else {          // L vertical (ll, -hl)
                    qee = top ? se1 : (se0 + se1);
                    qeo = top ? so1 : (so0 + so1);
                    qoe = fmaf(6.f, se1, se0 + se2);
                    qoo = fmaf(6.f, so1, so0 + so2);
                }
                acc00 = fmaf(W00[k], qee, acc00);
                acc01 = fmaf(W01[k], qeo, acc01);
                acc10 = fmaf(W10[k], qoe, acc10);
                acc11 = fmaf(W11[k], qoo, acc11);
            }
            a00[c] = acc00; a01[c] = acc01; a10[c] = acc10; a11[c] = acc11;
        }

        float4 r0 = make_float4(a00[0], a01[0], a00[1], a01[1]);
        float4 r1 = make_float4(a10[0], a11[0], a10[1], a11[1]);
        float* o0 = op + (size_t)(2 * y) * 1024 + 4 * gx;
        *(float4*)(o0)        = r0;
        *(float4*)(o0 + 1024) = r1;

        // shift rolling window
#pragma unroll
        for (int k = 0; k < 4; ++k)
#pragma unroll
            for (int c = 0; c < 2; ++c) {
                he[k][0][c] = he[k][1][c]; he[k][1][c] = he[k][2][c];
                ho[k][0][c] = ho[k][1][c]; ho[k][1][c] = ho[k][2][c];
            }
    }
}

extern "C" void kernel_launch(void* const* d_in, const int* in_sizes, int n_in,
                              void* d_out, int out_size)
{
    // x is the large input; the four 2x2 filters follow in metadata order.
    int ix = 0;
    for (int i = 0; i < n_in; ++i) {
        if (in_sizes[i] > 64) { ix = i; break; }
    }
    const float* xin = (const float*)d_in[ix];
    const float* f[4];
    int j = 0;
    for (int i = 0; i < n_in && j < 4; ++i)
        if (i != ix) f[j++] = (const float*)d_in[i];

    dim3 block(256, 1, 1);
    dim3 grid(1, H_IN / YS, 48);
    ihaar_kernel<<<grid, block>>>(xin, f[0], f[1], f[2], f[3], (float*)d_out);
}

// round 2
// speedup vs baseline: 1.2543x; 1.2543x over previous
#include <cuda_runtime.h>

// InverseHaarTransform collapsed to a separable 3x3 stencil on 512-res input.
// Band-pair fusion: P = sA*Lh(b0) + 0.5*sC*Gh(b2)   (vertical L applies)
//                   Q = sB*Lh(b1) + 0.5*sD*Gh(b3)   (vertical G applies)
// Per input row y -> output rows 2y,2y+1:
//   oee = (top? Pe1 : Pe0+Pe1) + 0.5*(top? -2*Qe1 : Qe0-Qe1)
//   oeo = same with Po,Qo
//   ooe = 0.25*(Pe0 + 6*Pe1 + Pe2 + Qe0 - Qe2)
//   ooo = 0.25*(Po0 + 6*Po1 + Po2 + Qo0 - Qo2)
// Horizontal primitives per raw row r[6] (left halo, 4 owned, right halo):
//   L: he[c]=r[c]+r[c+1] (x==0: r[1]),  ho[c]=r[c]+6r[c+1]+r[c+2]
//   G: ge[c]=r[c]-r[c+1] (x==0: -2r[1]), go[c]=r[c]-r[c+2]

#define YS 16
#define H_IN 512
#define W_IN 512

__global__ __launch_bounds__(256, 2)
void ihaar_kernel(const float* __restrict__ x,
                  const float* __restrict__ f0,
                  const float* __restrict__ f1,
                  const float* __restrict__ f2,
                  const float* __restrict__ f3,
                  float* __restrict__ out)
{
    const int tx = threadIdx.x;                       // 0..127 column quad
    const int z  = blockIdx.z;                        // b*3 + c
    const int b  = z / 3;
    const int cc = z - 3 * b;
    const int y0 = (blockIdx.y * 2 + threadIdx.y) * YS;

    const int  x2 = tx * 4;
    const int  xm = (x2 == 0) ? 0 : (x2 - 1);
    const int  xp = (x2 + 4 > W_IN - 1) ? (W_IN - 1) : (x2 + 4);
    const bool xe = (x2 == 0);

    const float* pl0 = x + ((size_t)(b * 12 + 0 * 3 + cc) << 18);
    const float* pl1 = x + ((size_t)(b * 12 + 1 * 3 + cc) << 18);
    const float* pl2 = x + ((size_t)(b * 12 + 2 * 3 + cc) << 18);
    const float* pl3 = x + ((size_t)(b * 12 + 3 * 3 + cc) << 18);

    float* op = out + ((size_t)z << 20);

    const float sA = __ldg(f0), sB = __ldg(f1), sC = __ldg(f2), sD = __ldg(f3);
    const float wPle = sA,          wPge = 0.5f  * sC;
    const float wPlo = 0.25f * sA,  wPgo = 0.25f * sC;
    const float wQle = sB,          wQge = 0.5f  * sD;
    const float wQlo = 0.25f * sB,  wQgo = 0.25f * sD;

    // Rolling 3-row window of fused horizontal combos.
    float Pe[3][4], Po[3][4], Qe[3][4], Qo[3][4];

    auto loadraw = [&](float r[4][6], int ry) {
        const float* rows[4] = { pl0 + ry * W_IN, pl1 + ry * W_IN,
                                 pl2 + ry * W_IN, pl3 + ry * W_IN };
#pragma unroll
        for (int k = 0; k < 4; ++k) {
            r[k][0] = __ldg(rows[k] + xm);
            float4 m = __ldg((const float4*)(rows[k] + x2));
            r[k][1] = m.x; r[k][2] = m.y; r[k][3] = m.z; r[k][4] = m.w;
            r[k][5] = __ldg(rows[k] + xp);
        }
    };

    auto buildPQ = [&](float* pe, float* po, float* qe, float* qo,
                       const float r[4][6]) {
#pragma unroll
        for (int c = 0; c < 4; ++c) {
            const bool ov = xe && (c == 0);
            float lhe0 = ov ? r[0][1]          : (r[0][c] + r[0][c + 1]);
            float ghe2 = ov ? (-2.f * r[2][1]) : (r[2][c] - r[2][c + 1]);
            float lho0 = fmaf(6.f, r[0][c + 1], r[0][c] + r[0][c + 2]);
            float gho2 = r[2][c] - r[2][c + 2];
            pe[c] = fmaf(wPle, lhe0, wPge * ghe2);
            po[c] = fmaf(wPlo, lho0, wPgo * gho2);

            float lhe1 = ov ? r[1][1]          : (r[1][c] + r[1][c + 1]);
            float ghe3 = ov ? (-2.f * r[3][1]) : (r[3][c] - r[3][c + 1]);
            float lho1 = fmaf(6.f, r[1][c + 1], r[1][c] + r[1][c + 2]);
            float gho3 = r[3][c] - r[3][c + 2];
            qe[c] = fmaf(wQle, lhe1, wQge * ghe3);
            qo[c] = fmaf(wQlo, lho1, wQgo * gho3);
        }
    };

    auto emit = [&](int y, bool top) {
        float oee[4], oeo[4], ooe[4], ooo[4];
#pragma unroll
        for (int c = 0; c < 4; ++c) {
            if (top) {
                oee[c] = Pe[1][c] - Qe[1][c];
                oeo[c] = Po[1][c] - Qo[1][c];
            } else {
                oee[c] = fmaf(0.5f, Qe[0][c] - Qe[1][c], Pe[0][c] + Pe[1][c]);
                oeo[c] = fmaf(0.5f, Qo[0][c] - Qo[1][c], Po[0][c] + Po[1][c]);
            }
            ooe[c] = 0.25f * (fmaf(6.f, Pe[1][c], Pe[0][c] + Pe[2][c])
                              + (Qe[0][c] - Qe[2][c]));
            ooo[c] = 0.25f * (fmaf(6.f, Po[1][c], Po[0][c] + Po[2][c])
                              + (Qo[0][c] - Qo[2][c]));
        }
        float* o0 = op + (size_t)(2 * y) * 1024 + 8 * tx;
        *(float4*)(o0)            = make_float4(oee[0], oeo[0], oee[1], oeo[1]);
        *(float4*)(o0 + 4)        = make_float4(oee[2], oeo[2], oee[3], oeo[3]);
        *(float4*)(o0 + 1024)     = make_float4(ooe[0], ooo[0], ooe[1], ooo[1]);
        *(float4*)(o0 + 1028)     = make_float4(ooe[2], ooo[2], ooe[3], ooo[3]);
    };

    auto shiftw = [&]() {
#pragma unroll
        for (int c = 0; c < 4; ++c) {
            Pe[0][c] = Pe[1][c]; Pe[1][c] = Pe[2][c];
            Po[0][c] = Po[1][c]; Po[1][c] = Po[2][c];
            Qe[0][c] = Qe[1][c]; Qe[1][c] = Qe[2][c];
            Qo[0][c] = Qo[1][c]; Qo[1][c] = Qo[2][c];
        }
    };

    float rA[4][6], rB[4][6];

    // Prologue: window rows 0,1 and prefetch row y0+1 into rA.
    loadraw(rA, (y0 == 0) ? 0 : (y0 - 1));
    buildPQ(Pe[0], Po[0], Qe[0], Qo[0], rA);
    loadraw(rA, y0);
    buildPQ(Pe[1], Po[1], Qe[1], Qo[1], rA);
    {
        int yn = (y0 + 1 > H_IN - 1) ? (H_IN - 1) : (y0 + 1);
        loadraw(rA, yn);
    }

    const bool topstrip = (y0 == 0);
#pragma unroll 2
    for (int yy = 0; yy < YS; yy += 2) {
        const int y = y0 + yy;
        // ---- first half: consume rA (row y+1), prefetch row y+2 into rB
        {
            int yn = (y + 2 > H_IN - 1) ? (H_IN - 1) : (y + 2);
            loadraw(rB, yn);
        }
        buildPQ(Pe[2], Po[2], Qe[2], Qo[2], rA);
        emit(y, topstrip && (yy == 0));
        shiftw();
        // ---- second half: consume rB (row y+2), prefetch row y+3 into rA
        {
            int yn = (y + 3 > H_IN - 1) ? (H_IN - 1) : (y + 3);
            loadraw(rA, yn);
        }
        buildPQ(Pe[2], Po[2], Qe[2], Qo[2], rB);
        emit(y + 1, false);
        shiftw();
    }
}

extern "C" void kernel_launch(void* const* d_in, const int* in_sizes, int n_in,
                              void* d_out, int out_size)
{
    int ix = 0;
    for (int i = 0; i < n_in; ++i)
        if (in_sizes[i] > 64) { ix = i; break; }
    const float* xin = (const float*)d_in[ix];
    const float* f[4];
    int j = 0;
    for (int i = 0; i < n_in && j < 4; ++i)
        if (i != ix) f[j++] = (const float*)d_in[i];

    dim3 block(128, 2, 1);
    dim3 grid(1, H_IN / (YS * 2), 48);
    ihaar_kernel<<<grid, block>>>(xin, f[0], f[1], f[2], f[3], (float*)d_out);
}

// round 3
// speedup vs baseline: 1.5118x; 1.2053x over previous
#include <cuda_runtime.h>

// InverseHaarTransform collapsed to a separable 3x3 stencil on the 512-res
// input, with band-pair fusion:
//   P = sA*Lh(b0) + 0.5*sC*Gh(b2)   (vertical L applies)
//   Q = sB*Lh(b1) + 0.5*sD*Gh(b3)   (vertical G applies)
// Per input row y -> output rows 2y, 2y+1:
//   even: oee = (top? P1 : P0+P1) + 0.5*(top? -2*Q1 : Q0-Q1)
//   odd : ooe = 0.25*(P0 + 6*P1 + P2 + Q0 - Q2)
// Horizontal primitives (a,b,c = cols x-1,x,x+1 clamped; zero-pad at x==0):
//   L: he = a+b (x==0: b),     ho = a+6b+c
//   G: ge = a-b (x==0: -2b),   go = a-c
//
// R3: cp.async pipeline. One CTA (256 thr) spans the full 512-col row.
// Stage = 2 rows x 4 bands x 512 f32 = 16KB; 3 stages = 48KB static smem.

#define YS    32
#define NP    (YS / 2 + 1)     // 17 row-pair stages (rows y0-1 .. y0+YS)
#define H_IN  512
#define W_IN  512

__global__ __launch_bounds__(256, 3)
void ihaar_kernel(const float* __restrict__ x,
                  const float* __restrict__ f0,
                  const float* __restrict__ f1,
                  const float* __restrict__ f2,
                  const float* __restrict__ f3,
                  float* __restrict__ out)
{
    __shared__ float sm[3][2][4][W_IN];   // [slot][rowhalf][band][col] = 48KB

    const int tx = threadIdx.x;           // 0..255, owns input cols 2tx,2tx+1
    const int z  = blockIdx.z;            // b*3 + c
    const int b  = z / 3;
    const int cc = z - 3 * b;
    const int y0 = blockIdx.y * YS;

    const int  x2 = tx * 2;
    const int  xm = (x2 == 0) ? 0 : (x2 - 1);
    const int  xp = (x2 + 2 > W_IN - 1) ? (W_IN - 1) : (x2 + 2);
    const bool xe = (x2 == 0);

    const float* pb0 = x + ((size_t)(b * 12 + 0 + cc) << 18);
    const float* pb1 = x + ((size_t)(b * 12 + 3 + cc) << 18);
    const float* pb2 = x + ((size_t)(b * 12 + 6 + cc) << 18);
    const float* pb3 = x + ((size_t)(b * 12 + 9 + cc) << 18);
    float* op = out + ((size_t)z << 20);

    const float sA = __ldg(f0), sB = __ldg(f1), sC = __ldg(f2), sD = __ldg(f3);
    const float wPle = sA,         wPge = 0.5f  * sC;
    const float wPlo = 0.25f * sA, wPgo = 0.25f * sC;
    const float wQle = sB,         wQge = 0.5f  * sD;
    const float wQlo = 0.25f * sB, wQgo = 0.25f * sD;

    // Fused rolling window: 3 rows x 2 cols per stream.
    float Pe[3][2], Po[3][2], Qe[3][2], Qo[3][2];

    // ---- async stage issue: rows (y0-1+2p, y0+2p), clamped ----
    auto issue = [&](int p) {
        const int slot = p % 3;
        const int r0   = y0 - 1 + 2 * p;
        const float* const pbs[4] = { pb0, pb1, pb2, pb3 };
#pragma unroll
        for (int k = 0; k < 4; ++k) {
            const int c    = tx + k * 256;        // chunk id 0..1023 (16B each)
            const int rh   = c >> 9;              // row half
            const int band = (c >> 7) & 3;
            const int off  = (c & 127) << 2;      // float offset
            int rr = r0 + rh;
            rr = rr < 0 ? 0 : (rr > H_IN - 1 ? H_IN - 1 : rr);
            const float* g = pbs[band] + (size_t)rr * W_IN + off;
            unsigned s = (unsigned)__cvta_generic_to_shared(&sm[slot][rh][band][off]);
            asm volatile("cp.async.cg.shared.global [%0], [%1], 16;\n"
                         :: "r"(s), "l"(g));
        }
        asm volatile("cp.async.commit_group;\n");
    };

#define BUILD(W, SLOT, RH) do {                                                \
    const float* r0_ = &sm[SLOT][RH][0][0];                                    \
    const float* r1_ = &sm[SLOT][RH][1][0];                                    \
    const float* r2_ = &sm[SLOT][RH][2][0];                                    \
    const float* r3_ = &sm[SLOT][RH][3][0];                                    \
    float2 v0 = *(const float2*)(r0_ + x2); float v0m = r0_[xm], v0p = r0_[xp];\
    float2 v1 = *(const float2*)(r1_ + x2); float v1m = r1_[xm], v1p = r1_[xp];\
    float2 v2 = *(const float2*)(r2_ + x2); float v2m = r2_[xm], v2p = r2_[xp];\
    float2 v3 = *(const float2*)(r3_ + x2); float v3m = r3_[xm], v3p = r3_[xp];\
    float lhe0a = xe ? v0.x : (v0m + v0.x);                                    \
    float lhe0b = v0.x + v0.y;                                                 \
    float lho0a = fmaf(6.f, v0.x, v0m + v0.y);                                 \
    float lho0b = fmaf(6.f, v0.y, v0.x + v0p);                                 \
    float ghe2a = xe ? (-2.f * v2.x) : (v2m - v2.x);                           \
    float ghe2b = v2.x - v2.y;                                                 \
    float gho2a = v2m - v2.y;                                                  \
    float gho2b = v2.x - v2p;                                                  \
    Pe[W][0] = fmaf(wPle, lhe0a, wPge * ghe2a);                                \
    Pe[W][1] = fmaf(wPle, lhe0b, wPge * ghe2b);                                \
    Po[W][0] = fmaf(wPlo, lho0a, wPgo * gho2a);                                \
    Po[W][1] = fmaf(wPlo, lho0b, wPgo * gho2b);                                \
    float lhe1a = xe ? v1.x : (v1m + v1.x);                                    \
    float lhe1b = v1.x + v1.y;                                                 \
    float lho1a = fmaf(6.f, v1.x, v1m + v1.y);                                 \
    float lho1b = fmaf(6.f, v1.y, v1.x + v1p);                                 \
    float ghe3a = xe ? (-2.f * v3.x) : (v3m - v3.x);                           \
    float ghe3b = v3.x - v3.y;                                                 \
    float gho3a = v3m - v3.y;                                                  \
    float gho3b = v3.x - v3p;                                                  \
    Qe[W][0] = fmaf(wQle, lhe1a, wQge * ghe3a);                                \
    Qe[W][1] = fmaf(wQle, lhe1b, wQge * ghe3b);                                \
    Qo[W][0] = fmaf(wQlo, lho1a, wQgo * gho3a);                                \
    Qo[W][1] = fmaf(wQlo, lho1b, wQgo * gho3b);                                \
} while (0)

    auto emit = [&](int y, bool top) {
        float oee[2], oeo[2], ooe[2], ooo[2];
#pragma unroll
        for (int c = 0; c < 2; ++c) {
            if (top) {
                oee[c] = Pe[1][c] - Qe[1][c];
                oeo[c] = Po[1][c] - Qo[1][c];
            } else {
                oee[c] = fmaf(0.5f, Qe[0][c] - Qe[1][c], Pe[0][c] + Pe[1][c]);
                oeo[c] = fmaf(0.5f, Qo[0][c] - Qo[1][c], Po[0][c] + Po[1][c]);
            }
            ooe[c] = 0.25f * (fmaf(6.f, Pe[1][c], Pe[0][c] + Pe[2][c])
                              + (Qe[0][c] - Qe[2][c]));
            ooo[c] = 0.25f * (fmaf(6.f, Po[1][c], Po[0][c] + Po[2][c])
                              + (Qo[0][c] - Qo[2][c]));
        }
        float* o0 = op + (size_t)(2 * y) * 1024 + 4 * tx;
        *(float4*)(o0)        = make_float4(oee[0], oeo[0], oee[1], oeo[1]);
        *(float4*)(o0 + 1024) = make_float4(ooe[0], ooo[0], ooe[1], ooo[1]);
    };

    auto shiftw = [&]() {
#pragma unroll
        for (int c = 0; c < 2; ++c) {
            Pe[0][c] = Pe[1][c]; Pe[1][c] = Pe[2][c];
            Po[0][c] = Po[1][c]; Po[1][c] = Po[2][c];
            Qe[0][c] = Qe[1][c]; Qe[1][c] = Qe[2][c];
            Qo[0][c] = Qo[1][c]; Qo[1][c] = Qo[2][c];
        }
    };

    // ---- prologue: stages 0,1 in flight; consume stage 0 (window rows 0,1)
    issue(0);
    issue(1);
    asm volatile("cp.async.wait_group 1;\n" ::: "memory");
    __syncthreads();
    BUILD(0, 0, 0);
    BUILD(1, 0, 1);
    __syncthreads();
    issue(2);

    const bool topstrip = (y0 == 0);

    for (int p = 1; p < NP; ++p) {
        if (p < NP - 1)
            asm volatile("cp.async.wait_group 1;\n" ::: "memory");
        else
            asm volatile("cp.async.wait_group 0;\n" ::: "memory");
        __syncthreads();

        const int slot = p % 3;
        const int y = y0 + 2 * p - 2;

        BUILD(2, slot, 0);
        emit(y, topstrip && (p == 1));
        shiftw();

        BUILD(2, slot, 1);
        emit(y + 1, false);
        shiftw();

        __syncthreads();
        if (p + 2 < NP) issue(p + 2);
    }
#undef BUILD
}

extern "C" void kernel_launch(void* const* d_in, const int* in_sizes, int n_in,
                              void* d_out, int out_size)
{
    int ix = 0;
    for (int i = 0; i < n_in; ++i)
        if (in_sizes[i] > 64) { ix = i; break; }
    const float* xin = (const float*)d_in[ix];
    const float* f[4];
    int j = 0;
    for (int i = 0; i < n_in && j < 4; ++i)
        if (i != ix) f[j++] = (const float*)d_in[i];

    dim3 block(256, 1, 1);
    dim3 grid(1, H_IN / YS, 48);
    ihaar_kernel<<<grid, block>>>(xin, f[0], f[1], f[2], f[3], (float*)d_out);
}